// round 5
// baseline (speedup 1.0000x reference)
#include <cuda_runtime.h>
#include <cuda_bf16.h>
#include <math.h>

// RoIPool: input [2,256,50,50] f32, rois [R,5] f32, out [R,256,7,7] f32.
// spatial_scale = 1/16; torchvision MaxRoiPool semantics (round-half-even,
// roi size >= 1, floor/ceil bin edges clipped to [0,W], empty bin -> 0).
//
// Design: setup kernel computes per-RoI bin tables once; main kernel is
// warp-per-(roi,channel) with warp-uniform loops. Lane l owns column x1+l,
// h-walk loads are coalesced, w-bin reduction via uniform shfl gathers.
// NOTE: w-bin edges are NOT bounded by roi_w (f32 ceil(7*bw) can exceed rw),
// so lane coverage is derived from max(we[j]) - x1, not roi_w.

#define PH 7
#define PW 7
#define SCALE 0.0625f
#define C_ 256
#define H_ 50
#define W_ 50
#define HW_ (H_ * W_)
#define MAXR 8192
#define NEG (-INFINITY)

struct RoiInfo {
    int base;       // b * C*H*W
    int x1;
    int cover;      // max_j(we[j]) - x1  (columns a warp must hold)
    int wspan;      // max w-bin width (uniform gather trip count)
    int ws[PW], we[PW], hs[PH], he[PH];
};

__device__ RoiInfo g_roi[MAXR];

__global__ void roi_setup(const float* __restrict__ rois, int R) {
    int r = blockIdx.x * blockDim.x + threadIdx.x;
    if (r >= R) return;
    const float* roi = rois + r * 5;
    int b  = (int)roi[0];
    int x1 = (int)rintf(roi[1] * SCALE);
    int y1 = (int)rintf(roi[2] * SCALE);
    int x2 = (int)rintf(roi[3] * SCALE);
    int y2 = (int)rintf(roi[4] * SCALE);
    int rw = max(x2 - x1 + 1, 1);
    int rh = max(y2 - y1 + 1, 1);
    float bw = (float)rw * (1.0f / PW);
    float bh = (float)rh * (1.0f / PH);

    RoiInfo info;
    info.base = b * (C_ * HW_);
    info.x1   = x1;
    int span = 1, maxe = x1;
#pragma unroll
    for (int j = 0; j < PW; j++) {
        int s = min(max((int)floorf((float)j * bw) + x1, 0), W_);
        int e = min(max((int)ceilf((float)(j + 1) * bw) + x1, 0), W_);
        info.ws[j] = s; info.we[j] = e;
        span = max(span, e - s);
        maxe = max(maxe, e);
    }
    info.wspan = span;
    info.cover = maxe - x1;
#pragma unroll
    for (int i = 0; i < PH; i++) {
        info.hs[i] = min(max((int)floorf((float)i * bh) + y1, 0), H_);
        info.he[i] = min(max((int)ceilf((float)(i + 1) * bh) + y1, 0), H_);
    }
    g_roi[r] = info;
}

__global__ void __launch_bounds__(256) roipool_main(const float* __restrict__ input,
                                                    float* __restrict__ out) {
    int gw   = (blockIdx.x * blockDim.x + threadIdx.x) >> 5;  // global warp id
    int lane = threadIdx.x & 31;
    int c = gw & (C_ - 1);
    int r = gw >> 8;                 // C_ == 256

    const RoiInfo& info = g_roi[r];
    int x1    = info.x1;
    int cover = info.cover;
    int wspan = info.wspan;

    const float* pc = input + info.base + c * HW_ + (x1 + lane);
    bool valid  = (x1 + lane < W_);                 // edges are clipped to W
    bool two    = cover > 32;                       // rare fallback
    bool valid2 = two && (x1 + lane + 32 < W_) && (lane + 32 < cover);

    // per-lane w-bin edges (lane < 7 meaningful)
    int li  = lane < PW ? lane : 0;
    int wsl = info.ws[li];
    int wel = info.we[li];
    int span = wel - wsl;

    int outbase = gw * (PH * PW);

#pragma unroll
    for (int ph = 0; ph < PH; ph++) {
        int h0 = info.hs[ph];
        int h1 = info.he[ph];

        // column max over this h strip (uniform trip count, coalesced loads)
        float cm  = NEG;
        float cm2 = NEG;
        for (int h = h0; h < h1; h++) {
            float v = valid ? pc[h * W_] : NEG;
            cm = fmaxf(cm, v);
            if (two) {
                float v2 = valid2 ? pc[h * W_ + 32] : NEG;
                cm2 = fmaxf(cm2, v2);
            }
        }

        // reduce across the w-bin owned by lane==pw (uniform shfl loop)
        float m = NEG;
        for (int k = 0; k < wspan; k++) {
            int idx = wsl + k;
            if (idx >= wel) idx = wel - 1;       // clamp (unused if k>=span)
            int src = idx - x1;
            float v = __shfl_sync(0xffffffffu, cm, src & 31);
            if (two) {
                float vb = __shfl_sync(0xffffffffu, cm2, src & 31);
                if (src >= 32) v = vb;
            }
            if (k < span) m = fmaxf(m, v);
        }

        if (m == NEG) m = 0.0f;                  // empty bin -> 0
        if (lane < PW) out[outbase + ph * PW + lane] = m;
    }
}

extern "C" void kernel_launch(void* const* d_in, const int* in_sizes, int n_in,
                              void* d_out, int out_size) {
    const float* input = (const float*)d_in[0];
    const float* rois  = (const float*)d_in[1];
    float* out = (float*)d_out;

    int R = in_sizes[1] / 5;

    roi_setup<<<(R + 255) / 256, 256>>>(rois, R);

    int total_warps = R * C_;
    int threads = 256;
    int blocks = (total_warps * 32 + threads - 1) / threads;
    roipool_main<<<blocks, threads>>>(input, out);
}

// round 9
// speedup vs baseline: 1.1792x; 1.1792x over previous
#include <cuda_runtime.h>
#include <cuda_bf16.h>
#include <stdint.h>
#include <math.h>

// RoIPool: input [N=2,C=256,H=50,W=50] f32, rois [R,5] f32, out [R,256,7,7] f32.
// spatial_scale=1/16; torchvision MaxRoiPool semantics.
//
// Pipeline:
//   1) transpose input -> channel-last [N,H,W,C] (coalesced channel loads)
//   2) setup: per-RoI 49 packed bin edges (ws|we<<8|hs<<16|he<<24)
//   3) main: block=(roi, c-half, bin-half); thread=channel. Block-uniform bin
//      loops, coalesced loads, smem-staged coalesced output.

typedef unsigned int u32;

#define PH 7
#define PW 7
#define BINS 49
#define SCALE 0.0625f
#define C_ 256
#define H_ 50
#define W_ 50
#define HW_ (H_ * W_)
#define CHW_ (C_ * HW_)
#define MAXR 8192
#define MAXN 4

__device__ float g_inT[MAXN * HW_ * C_];     // [N][H][W][C]
__device__ u32   g_bins[MAXR * BINS];        // packed ws|we<<8|hs<<16|he<<24
__device__ int   g_img[MAXR];

// ---------------- transpose [N,C,HW] -> [N,HW,C] ----------------
__global__ void transpose_k(const float* __restrict__ in) {
    __shared__ float t[32][33];
    int b  = blockIdx.z;
    int s0 = blockIdx.x * 32;   // hw tile
    int c0 = blockIdx.y * 32;   // channel tile
    int x = threadIdx.x, y = threadIdx.y;

#pragma unroll
    for (int j = 0; j < 32; j += 8) {
        int c = c0 + y + j, s = s0 + x;
        if (s < HW_) t[y + j][x] = in[b * CHW_ + c * HW_ + s];
    }
    __syncthreads();
#pragma unroll
    for (int j = 0; j < 32; j += 8) {
        int s = s0 + y + j, c = c0 + x;
        if (s < HW_) g_inT[b * CHW_ + s * C_ + c] = t[x][y + j];
    }
}

// ---------------- per-RoI bin table ----------------
__global__ void roi_setup(const float* __restrict__ rois, int R) {
    int r = blockIdx.x * blockDim.x + threadIdx.x;
    if (r >= R) return;
    const float* roi = rois + r * 5;
    int b  = (int)roi[0];
    int x1 = (int)rintf(roi[1] * SCALE);
    int y1 = (int)rintf(roi[2] * SCALE);
    int x2 = (int)rintf(roi[3] * SCALE);
    int y2 = (int)rintf(roi[4] * SCALE);
    int rw = max(x2 - x1 + 1, 1);
    int rh = max(y2 - y1 + 1, 1);
    float bw = (float)rw * (1.0f / PW);
    float bh = (float)rh * (1.0f / PH);

    g_img[r] = b;

    int ws[PW], we[PW], hs[PH], he[PH];
#pragma unroll
    for (int j = 0; j < PW; j++) {
        ws[j] = min(max((int)floorf((float)j * bw) + x1, 0), W_);
        we[j] = min(max((int)ceilf((float)(j + 1) * bw) + x1, 0), W_);
    }
#pragma unroll
    for (int i = 0; i < PH; i++) {
        hs[i] = min(max((int)floorf((float)i * bh) + y1, 0), H_);
        he[i] = min(max((int)ceilf((float)(i + 1) * bh) + y1, 0), H_);
    }
#pragma unroll
    for (int i = 0; i < PH; i++)
#pragma unroll
        for (int j = 0; j < PW; j++) {
            u32 p = (u32)ws[j] | ((u32)we[j] << 8) |
                    ((u32)hs[i] << 16) | ((u32)he[i] << 24);
            g_bins[r * BINS + i * PW + j] = p;
        }
}

// ---------------- main pooling ----------------
#define TPAD 27   // smem stride (odd -> conflict-free), >= 25

template <int NB>
__device__ __forceinline__ void pool_body(int r, int half, int bin0,
                                          float* __restrict__ out) {
    __shared__ float tile[128 * TPAD];
    int tid = threadIdx.x;
    int c = half * 128 + tid;
    const float* base = g_inT + g_img[r] * CHW_ + c;
    const u32* bp = g_bins + r * BINS + bin0;

    for (int bi = 0; bi < NB; ++bi) {
        u32 p = bp[bi];
        int ws = p & 0xff, we = (p >> 8) & 0xff;
        int hs = (p >> 16) & 0xff, he = p >> 24;
        float acc = -INFINITY;
        for (int h = hs; h < he; ++h) {
            const float* rp = base + (h * W_ + ws) * C_;
            for (int w = ws; w < we; ++w) {
                acc = fmaxf(acc, *rp);
                rp += C_;
            }
        }
        tile[tid * TPAD + bi] = (he <= hs || we <= ws) ? 0.0f : acc;
    }
    __syncthreads();

    // coalesced copyout: out[r][c][bin], 128 channels x NB bins
    float* outp = out + (size_t)(r * C_ + half * 128) * BINS + bin0;
    for (int i = tid; i < 128 * NB; i += 128) {
        int cl = i / NB;
        int bb = i - cl * NB;
        outp[cl * BINS + bb] = tile[cl * TPAD + bb];
    }
}

__global__ void __launch_bounds__(128) roipool_main(float* __restrict__ out) {
    int r    = blockIdx.x;
    int half = blockIdx.y >> 1;
    int bh   = blockIdx.y & 1;
    if (bh == 0) pool_body<25>(r, half, 0, out);
    else         pool_body<24>(r, half, 25, out);
}

// ---------------- launch ----------------
extern "C" void kernel_launch(void* const* d_in, const int* in_sizes, int n_in,
                              void* d_out, int out_size) {
    const float* input = (const float*)d_in[0];
    const float* rois  = (const float*)d_in[1];
    float* out = (float*)d_out;

    int N = in_sizes[0] / CHW_;
    int R = in_sizes[1] / 5;

    dim3 tg((HW_ + 31) / 32, C_ / 32, N);
    transpose_k<<<tg, dim3(32, 8)>>>(input);

    roi_setup<<<(R + 127) / 128, 128>>>(rois, R);

    roipool_main<<<dim3(R, 4), 128>>>(out);
}

// round 11
// speedup vs baseline: 2.0224x; 1.7151x over previous
#include <cuda_runtime.h>
#include <cuda_bf16.h>
#include <stdint.h>
#include <math.h>

// RoIPool: input [N=2,C=256,H=50,W=50] f32, rois [R,5] f32, out [R,256,7,7] f32.
// spatial_scale=1/16; torchvision MaxRoiPool semantics (round-half-even,
// roi size >= 1, floor/ceil bin edges clipped to [0,W]/[0,H], empty bin -> 0).
//
// Design: setup kernel computes, per (roi, bin), a packed descriptor
//   word0 = start(hs*W+ws, 12b) | wlen<<12 (6b) | hlen<<18 (6b)
//   word1 = b * C*H*W  (image base offset)
// Main kernel: one thread per output element (R*C*49 = 3.2M threads for
// latency hiding), NCHW layout, minimal per-thread ALU.

typedef unsigned int u32;

#define PH 7
#define PW 7
#define BINS 49
#define SCALE 0.0625f
#define C_ 256
#define H_ 50
#define W_ 50
#define HW_ (H_ * W_)
#define CHW_ (C_ * HW_)
#define MAXR 8192

__device__ uint2 g_tab[MAXR * BINS];

__global__ void roi_setup(const float* __restrict__ rois, int R) {
    int r = blockIdx.x * blockDim.x + threadIdx.x;
    if (r >= R) return;
    const float* roi = rois + r * 5;
    int b  = (int)roi[0];
    int x1 = (int)rintf(roi[1] * SCALE);
    int y1 = (int)rintf(roi[2] * SCALE);
    int x2 = (int)rintf(roi[3] * SCALE);
    int y2 = (int)rintf(roi[4] * SCALE);
    int rw = max(x2 - x1 + 1, 1);
    int rh = max(y2 - y1 + 1, 1);
    float bw = (float)rw * (1.0f / PW);
    float bh = (float)rh * (1.0f / PH);

    int ws[PW], we[PW], hs[PH], he[PH];
#pragma unroll
    for (int j = 0; j < PW; j++) {
        ws[j] = min(max((int)floorf((float)j * bw) + x1, 0), W_);
        we[j] = min(max((int)ceilf((float)(j + 1) * bw) + x1, 0), W_);
    }
#pragma unroll
    for (int i = 0; i < PH; i++) {
        hs[i] = min(max((int)floorf((float)i * bh) + y1, 0), H_);
        he[i] = min(max((int)ceilf((float)(i + 1) * bh) + y1, 0), H_);
    }

    int base = b * CHW_;
#pragma unroll
    for (int i = 0; i < PH; i++) {
#pragma unroll
        for (int j = 0; j < PW; j++) {
            int wl = we[j] - ws[j];        // >= 0 after clipping
            int hl = he[i] - hs[i];
            u32 p = (u32)(hs[i] * W_ + ws[j]) | ((u32)wl << 12) | ((u32)hl << 18);
            g_tab[r * BINS + i * PW + j] = make_uint2(p, (u32)base);
        }
    }
}

__global__ void __launch_bounds__(256) roipool_main(const float* __restrict__ input,
                                                    float* __restrict__ out,
                                                    int total) {
    int idx = blockIdx.x * blockDim.x + threadIdx.x;
    if (idx >= total) return;

    u32 rc  = (u32)idx / BINS;           // compiler emits exact magic-mul
    u32 bin = (u32)idx - rc * BINS;
    u32 r = rc >> 8;                     // C_ == 256
    u32 c = rc & (C_ - 1);

    uint2 t = g_tab[r * BINS + bin];
    int start = t.x & 4095;
    int wl = (t.x >> 12) & 63;
    int hl = (int)(t.x >> 18);

    const float* p = input + t.y + c * HW_ + start;

    float m = -INFINITY;
    for (int i = 0; i < hl; ++i) {
        for (int j = 0; j < wl; ++j) {
            m = fmaxf(m, p[j]);
        }
        p += W_;
    }
    if (m == -INFINITY) m = 0.0f;   // empty bin
    out[idx] = m;
}

extern "C" void kernel_launch(void* const* d_in, const int* in_sizes, int n_in,
                              void* d_out, int out_size) {
    const float* input = (const float*)d_in[0];
    const float* rois  = (const float*)d_in[1];
    float* out = (float*)d_out;

    int R = in_sizes[1] / 5;
    int total = R * C_ * BINS;

    roi_setup<<<(R + 127) / 128, 128>>>(rois, R);

    int threads = 256;
    int blocks = (total + threads - 1) / threads;
    roipool_main<<<blocks, threads>>>(input, out, total);
}

// round 12
// speedup vs baseline: 2.4217x; 1.1974x over previous
#include <cuda_runtime.h>
#include <cuda_bf16.h>
#include <stdint.h>
#include <math.h>

// RoIPool: input [N,256,50,50] f32, rois [R,5] f32, out [R,256,7,7] f32.
// spatial_scale=1/16; torchvision MaxRoiPool semantics (round-half-even,
// roi size >= 1, floor/ceil bin edges clipped to [0,W]/[0,H], empty bin -> 0).
//
// Design:
//  1) transpose NCHW -> NHWC (lanes=channels => coalesced cell loads)
//  2) main: block=(roi, 32-channel group), 224 threads = 7 warps.
//     warp w handles ph=w; all bin loop bounds are warp-uniform scalars ->
//     zero divergence; each window cell load is one 128B line.
//     Results staged in padded smem, written out as one contiguous
//     coalesced 32*49-float block.

typedef unsigned int u32;

#define PH 7
#define PW 7
#define BINS 49
#define SCALE 0.0625f
#define C_ 256
#define H_ 50
#define W_ 50
#define HW_ (H_ * W_)
#define CHW_ (C_ * HW_)
#define MAXN 4

__device__ float g_inT[MAXN * HW_ * C_];   // [N][H][W][C]

// ---------------- transpose [N,C,HW] -> [N,HW,C] ----------------
__global__ void transpose_k(const float* __restrict__ in) {
    __shared__ float t[32][33];
    int b  = blockIdx.z;
    int s0 = blockIdx.x * 32;   // hw tile
    int c0 = blockIdx.y * 32;   // channel tile
    int x = threadIdx.x, y = threadIdx.y;

#pragma unroll
    for (int j = 0; j < 32; j += 8) {
        int c = c0 + y + j, s = s0 + x;
        if (s < HW_) t[y + j][x] = in[b * CHW_ + c * HW_ + s];
    }
    __syncthreads();
#pragma unroll
    for (int j = 0; j < 32; j += 8) {
        int s = s0 + y + j, c = c0 + x;
        if (s < HW_) g_inT[b * CHW_ + s * C_ + c] = t[x][y + j];
    }
}

// ---------------- main pooling ----------------
// block: x = roi, y = channel group (8 groups of 32). 224 threads (7 warps).
__global__ void __launch_bounds__(224) roipool_main(const float* __restrict__ rois,
                                                    float* __restrict__ out) {
    __shared__ int sWs[PW], sWe[PW], sHs[PH], sHe[PH];
    __shared__ int sBase;
    __shared__ float sOut[BINS * 33];   // [bin][32ch] padded to 33

    int r   = blockIdx.x;
    int cg  = blockIdx.y;               // channel group
    int tid = threadIdx.x;
    int wid = tid >> 5;                 // 0..6 == ph
    int lane = tid & 31;

    // ---- per-RoI bin edges (threads 0..6 compute column j and row i = tid) ----
    if (tid < PW) {
        const float* roi = rois + r * 5;
        float f0 = roi[0], f1 = roi[1], f2 = roi[2], f3 = roi[3], f4 = roi[4];
        int x1 = (int)rintf(f1 * SCALE);
        int y1 = (int)rintf(f2 * SCALE);
        int x2 = (int)rintf(f3 * SCALE);
        int y2 = (int)rintf(f4 * SCALE);
        int rw = max(x2 - x1 + 1, 1);
        int rh = max(y2 - y1 + 1, 1);
        float bw = (float)rw * (1.0f / PW);
        float bh = (float)rh * (1.0f / PH);
        int j = tid;
        sWs[j] = min(max((int)floorf((float)j * bw) + x1, 0), W_);
        sWe[j] = min(max((int)ceilf((float)(j + 1) * bw) + x1, 0), W_);
        sHs[j] = min(max((int)floorf((float)j * bh) + y1, 0), H_);
        sHe[j] = min(max((int)ceilf((float)(j + 1) * bh) + y1, 0), H_);
        if (tid == 0) sBase = (int)f0 * CHW_;
    }
    __syncthreads();

    // ---- pooling: warp wid handles ph = wid; lanes = 32 channels ----
    int c = cg * 32 + lane;
    const float* base = g_inT + sBase + c;
    int h0 = sHs[wid];
    int h1 = sHe[wid];

#pragma unroll
    for (int pw = 0; pw < PW; ++pw) {
        int ws = sWs[pw];
        int we = sWe[pw];
        float acc = -INFINITY;
        for (int h = h0; h < h1; ++h) {
            const float* rp = base + (h * W_ + ws) * C_;
            for (int w = ws; w < we; ++w) {
                acc = fmaxf(acc, *rp);
                rp += C_;
            }
        }
        if (acc == -INFINITY) acc = 0.0f;    // empty bin
        sOut[(wid * PW + pw) * 33 + lane] = acc;
    }
    __syncthreads();

    // ---- coalesced copyout: out[r][cg*32 + cc][bin], 32*49 contiguous floats ----
    float* outp = out + ((size_t)r * C_ + cg * 32) * BINS;
    for (int e = tid; e < 32 * BINS; e += 224) {
        int cc  = e / BINS;                  // compiler magic-div
        int bin = e - cc * BINS;
        outp[e] = sOut[bin * 33 + cc];
    }
}

// ---------------- launch ----------------
extern "C" void kernel_launch(void* const* d_in, const int* in_sizes, int n_in,
                              void* d_out, int out_size) {
    const float* input = (const float*)d_in[0];
    const float* rois  = (const float*)d_in[1];
    float* out = (float*)d_out;

    int N = in_sizes[0] / CHW_;
    int R = in_sizes[1] / 5;

    dim3 tg((HW_ + 31) / 32, C_ / 32, N);
    transpose_k<<<tg, dim3(32, 8)>>>(input);

    roipool_main<<<dim3(R, 8), 224>>>(rois, out);
}